// round 1
// baseline (speedup 1.0000x reference)
#include <cuda_runtime.h>
#include <math.h>

#define BATCH 2
#define SEQ   2048
#define DM    1024
#define NH    16
#define DK    64

// Scratch (device globals — no allocations allowed)
__device__ float g_Q[BATCH * SEQ * DM];
__device__ float g_K[BATCH * SEQ * DM];
__device__ float g_V[BATCH * SEQ * DM];
__device__ float g_C[BATCH * SEQ * DM];

// ---------------------------------------------------------------------------
// GEMM: C[M,N] = A[M,K] @ W[N,K]^T + b[N]   (nn.Linear semantics)
// 64x64 tile, BK=16, 16x16 threads, 4x4 per thread.
// ---------------------------------------------------------------------------
__global__ __launch_bounds__(256) void gemm_bias_kernel(
    const float* __restrict__ A, const float* __restrict__ W,
    const float* __restrict__ b, float* __restrict__ C,
    int M, int N, int K)
{
    __shared__ float As[16][65];   // [k][m], padded to kill store conflicts
    __shared__ float Ws[16][65];   // [k][n]

    const int tx = threadIdx.x;          // 0..15 -> n
    const int ty = threadIdx.y;          // 0..15 -> m
    const int tid = ty * 16 + tx;
    const int n0 = blockIdx.x * 64;
    const int m0 = blockIdx.y * 64;

    float acc[4][4] = {};

    for (int k0 = 0; k0 < K; k0 += 16) {
        #pragma unroll
        for (int i = 0; i < 4; i++) {
            int idx = i * 256 + tid;          // 0..1023
            int r = idx >> 4;                 // 0..63
            int c = idx & 15;                 // 0..15
            As[c][r] = A[(size_t)(m0 + r) * K + k0 + c];
            Ws[c][r] = W[(size_t)(n0 + r) * K + k0 + c];
        }
        __syncthreads();

        #pragma unroll
        for (int kk = 0; kk < 16; kk++) {
            float a[4], w[4];
            #pragma unroll
            for (int i = 0; i < 4; i++) a[i] = As[kk][ty * 4 + i];
            #pragma unroll
            for (int j = 0; j < 4; j++) w[j] = Ws[kk][tx * 4 + j];
            #pragma unroll
            for (int i = 0; i < 4; i++)
                #pragma unroll
                for (int j = 0; j < 4; j++)
                    acc[i][j] += a[i] * w[j];
        }
        __syncthreads();
    }

    #pragma unroll
    for (int i = 0; i < 4; i++) {
        int m = m0 + ty * 4 + i;
        #pragma unroll
        for (int j = 0; j < 4; j++) {
            int n = n0 + tx * 4 + j;
            C[(size_t)m * N + n] = acc[i][j] + b[n];
        }
    }
}

// ---------------------------------------------------------------------------
// Flash attention (fp32): per block = (q-tile of 128, head, batch).
// Each thread owns one query row: q[64] and o[64] in registers,
// KV tiles of 32 staged in smem, scores staged in padded smem.
// ---------------------------------------------------------------------------
#define QT 128
#define KT 32

__global__ __launch_bounds__(QT) void flash_attn_kernel()
{
    __shared__ float Ks[KT][DK];        // 8 KB
    __shared__ float Vs[KT][DK];        // 8 KB
    __shared__ float Ss[QT][KT + 1];    // 16.5 KB, stride 33 -> conflict-free

    const int tid = threadIdx.x;
    const int b   = blockIdx.z;
    const int h   = blockIdx.y;
    const int q   = blockIdx.x * QT + tid;

    const float* qptr = g_Q + ((size_t)(b * SEQ + q)) * DM + h * DK;

    float qr[DK];
    #pragma unroll
    for (int d = 0; d < DK; d++) qr[d] = qptr[d] * 0.125f;   // 1/sqrt(64)

    float o[DK];
    #pragma unroll
    for (int d = 0; d < DK; d++) o[d] = 0.0f;
    float m = -1e30f, l = 0.0f;

    for (int kv0 = 0; kv0 < SEQ; kv0 += KT) {
        // cooperative load of K/V tile (coalesced over d)
        for (int i = tid; i < KT * DK; i += QT) {
            int r = i >> 6;           // /64
            int c = i & 63;
            size_t g = ((size_t)(b * SEQ + kv0 + r)) * DM + h * DK + c;
            Ks[r][c] = g_K[g];
            Vs[r][c] = g_V[g];
        }
        __syncthreads();

        // pass 1: scores for this tile
        float tmax = -1e30f;
        for (int j = 0; j < KT; j++) {
            float acc = 0.0f;
            #pragma unroll
            for (int d = 0; d < DK; d++) acc += qr[d] * Ks[j][d];
            Ss[tid][j] = acc;
            tmax = fmaxf(tmax, acc);
        }

        // online softmax rescale
        float mn = fmaxf(m, tmax);
        float corr = __expf(m - mn);
        m = mn;
        l *= corr;
        #pragma unroll
        for (int d = 0; d < DK; d++) o[d] *= corr;

        // pass 2: accumulate P @ V
        for (int j = 0; j < KT; j++) {
            float p = __expf(Ss[tid][j] - mn);
            l += p;
            #pragma unroll
            for (int d = 0; d < DK; d++) o[d] += p * Vs[j][d];
        }
        __syncthreads();
    }

    float inv = 1.0f / l;
    float* optr = g_C + ((size_t)(b * SEQ + q)) * DM + h * DK;
    #pragma unroll
    for (int d = 0; d < DK; d++) optr[d] = o[d] * inv;
}

// ---------------------------------------------------------------------------
// Launch
// ---------------------------------------------------------------------------
extern "C" void kernel_launch(void* const* d_in, const int* in_sizes, int n_in,
                              void* d_out, int out_size)
{
    const float* x  = (const float*)d_in[0];
    const float* Wq = (const float*)d_in[1];
    const float* bq = (const float*)d_in[2];
    const float* Wk = (const float*)d_in[3];
    const float* bk = (const float*)d_in[4];
    const float* Wv = (const float*)d_in[5];
    const float* bv = (const float*)d_in[6];
    const float* Wo = (const float*)d_in[7];
    const float* bo = (const float*)d_in[8];
    float* out = (float*)d_out;

    float *Qp, *Kp, *Vp, *Cp;
    cudaGetSymbolAddress((void**)&Qp, g_Q);
    cudaGetSymbolAddress((void**)&Kp, g_K);
    cudaGetSymbolAddress((void**)&Vp, g_V);
    cudaGetSymbolAddress((void**)&Cp, g_C);

    const int M = BATCH * SEQ;   // 4096
    dim3 gblock(16, 16);
    dim3 ggrid(DM / 64, M / 64); // (16, 64)

    gemm_bias_kernel<<<ggrid, gblock>>>(x, Wq, bq, Qp, M, DM, DM);
    gemm_bias_kernel<<<ggrid, gblock>>>(x, Wk, bk, Kp, M, DM, DM);
    gemm_bias_kernel<<<ggrid, gblock>>>(x, Wv, bv, Vp, M, DM, DM);

    dim3 agrid(SEQ / QT, NH, BATCH); // (16, 16, 2)
    flash_attn_kernel<<<agrid, QT>>>();

    gemm_bias_kernel<<<ggrid, gblock>>>(Cp, Wo, bo, out, M, DM, DM);
}

// round 3
// speedup vs baseline: 7.4164x; 7.4164x over previous
#include <cuda_runtime.h>
#include <cuda_fp16.h>
#include <math.h>
#include <stdint.h>

#define BATCH 2
#define SEQ   2048
#define DM    1024
#define NH    16
#define DK    64
#define MROWS (BATCH * SEQ)   // 4096
#define L2E   1.44269504f

// ---------------------------------------------------------------------------
// Scratch (device globals — no allocations allowed)
// ---------------------------------------------------------------------------
__device__ __half g_xh[MROWS * DM];
__device__ __half g_xl[MROWS * DM];
__device__ __half g_q [MROWS * DM];   // pre-scaled by 1/8
__device__ __half g_k [MROWS * DM];
__device__ __half g_vh[MROWS * DM];
__device__ __half g_vl[MROWS * DM];
__device__ __half g_ch[MROWS * DM];
__device__ __half g_cl[MROWS * DM];
__device__ __half g_wqh[DM * DM];
__device__ __half g_wkh[DM * DM];
__device__ __half g_wvh[DM * DM];
__device__ __half g_wvl[DM * DM];
__device__ __half g_woh[DM * DM];
__device__ __half g_wol[DM * DM];

// ---------------------------------------------------------------------------
// Base-ISA PTX helpers (compute_103-safe: mma.sync / ldmatrix / cp.async)
// ---------------------------------------------------------------------------
__device__ __forceinline__ uint32_t smem_u32(const void* p) {
    uint32_t a;
    asm("{ .reg .u64 t; cvta.to.shared.u64 t, %1; cvt.u32.u64 %0, t; }"
        : "=r"(a) : "l"(p));
    return a;
}

#define CP_ASYNC16(dst, src) \
    asm volatile("cp.async.cg.shared.global [%0], [%1], 16;" \
                 :: "r"(dst), "l"(src) : "memory")
#define CP_COMMIT() asm volatile("cp.async.commit_group;" ::: "memory")
#define CP_WAIT1()  asm volatile("cp.async.wait_group 1;" ::: "memory")

__device__ __forceinline__ void ldsm4(uint32_t* r, uint32_t addr) {
    asm volatile("ldmatrix.sync.aligned.m8n8.x4.shared.b16 {%0,%1,%2,%3}, [%4];"
                 : "=r"(r[0]), "=r"(r[1]), "=r"(r[2]), "=r"(r[3]) : "r"(addr));
}
__device__ __forceinline__ void ldsm4t(uint32_t* r, uint32_t addr) {
    asm volatile("ldmatrix.sync.aligned.m8n8.x4.trans.shared.b16 {%0,%1,%2,%3}, [%4];"
                 : "=r"(r[0]), "=r"(r[1]), "=r"(r[2]), "=r"(r[3]) : "r"(addr));
}

__device__ __forceinline__ void mma16816(float* c, const uint32_t* a,
                                         const uint32_t* b) {
    asm volatile(
        "mma.sync.aligned.m16n8k16.row.col.f32.f16.f16.f32 "
        "{%0,%1,%2,%3},{%4,%5,%6,%7},{%8,%9},{%0,%1,%2,%3};"
        : "+f"(c[0]), "+f"(c[1]), "+f"(c[2]), "+f"(c[3])
        : "r"(a[0]), "r"(a[1]), "r"(a[2]), "r"(a[3]), "r"(b[0]), "r"(b[1]));
}

__device__ __forceinline__ float ex2f(float x) {
    float y;
    asm("ex2.approx.f32 %0, %1;" : "=f"(y) : "f"(x));
    return y;
}

__device__ __forceinline__ uint32_t packh2(__half a, __half b) {
    __half2 t = __halves2half2(a, b);
    return *reinterpret_cast<uint32_t*>(&t);
}

// swizzled smem offset for (row, 16B-unit): rows are 8 units (128B) wide
__device__ __forceinline__ uint32_t swz(int row, int un) {
    return (uint32_t)(((row << 3) + (un ^ (row & 7))) << 4);
}

// ---------------------------------------------------------------------------
// split fp32 -> fp16 hi (+ optional lo)
// ---------------------------------------------------------------------------
__global__ void split_kernel(const float* __restrict__ in,
                             __half* __restrict__ hi,
                             __half* __restrict__ lo, int n) {
    int i = blockIdx.x * 256 + threadIdx.x;
    if (i < n) {
        float v = in[i];
        __half h = __float2half_rn(v);
        hi[i] = h;
        if (lo) lo[i] = __float2half_rn(v - __half2float(h));
    }
}

// ---------------------------------------------------------------------------
// HMMA GEMM: C[M,N] = A[M,K] @ W[N,K]^T + bias
// PASSES=1: ah*bh.  PASSES=3: ah*bh + ah*bl + al*bh (fp32 accum throughout).
// EPI: 0 = fp32 out; 1 = fp16 out (scaled); 2 = fp16 hi/lo pair out.
// Block tile 128x128, BK=64, 8 warps (warp tile 32x64), cp.async double buffer.
// ---------------------------------------------------------------------------
__device__ __forceinline__ void cp_tile(uint32_t dstBase, const __half* src,
                                        int rowBase, int K, int kc, int tid) {
    #pragma unroll
    for (int it = 0; it < 4; ++it) {
        int u = tid + it * 256;
        int row = u >> 3, un = u & 7;
        const __half* g = src + (size_t)(rowBase + row) * K + kc * 64 + un * 8;
        CP_ASYNC16(dstBase + swz(row, un), g);
    }
}

template <int PASSES, int EPI>
__global__ __launch_bounds__(256) void gemm_mma(
    const __half* __restrict__ Ah, const __half* __restrict__ Al,
    const __half* __restrict__ Bh, const __half* __restrict__ Bl,
    const float* __restrict__ bias,
    __half* __restrict__ o16a, __half* __restrict__ o16b,
    float* __restrict__ o32, int M, int N, int K, float oscale) {
    extern __shared__ char sm[];
    const uint32_t sb = smem_u32(sm);
    const int NT = (PASSES == 3) ? 4 : 2;
    const uint32_t stageB = (uint32_t)NT * 16384u;
    const int tid = threadIdx.x, wid = tid >> 5, lane = tid & 31;
    const int n0 = blockIdx.x * 128, m0 = blockIdx.y * 128;
    const int wm = (wid & 3) * 32, wn = (wid >> 2) * 64;
    const int NKC = K / 64;

    float acc[2][8][4];
    #pragma unroll
    for (int i = 0; i < 2; i++)
        #pragma unroll
        for (int f = 0; f < 8; f++)
            #pragma unroll
            for (int r = 0; r < 4; r++) acc[i][f][r] = 0.0f;

    // prologue: stages 0, 1
    #pragma unroll
    for (int s = 0; s < 2; s++) {
        uint32_t base = sb + s * stageB;
        if (PASSES == 3) {
            cp_tile(base,          Ah, m0, K, s, tid);
            cp_tile(base + 16384,  Al, m0, K, s, tid);
            cp_tile(base + 32768,  Bh, n0, K, s, tid);
            cp_tile(base + 49152,  Bl, n0, K, s, tid);
        } else {
            cp_tile(base,          Ah, m0, K, s, tid);
            cp_tile(base + 16384,  Bh, n0, K, s, tid);
        }
        CP_COMMIT();
    }

    for (int kc = 0; kc < NKC; kc++) {
        CP_WAIT1();
        __syncthreads();
        const uint32_t base = sb + (kc & 1) * stageB;

        #pragma unroll
        for (int p = 0; p < PASSES; p++) {
            const uint32_t aOff = (PASSES == 3 && p == 2) ? 16384u : 0u;
            const uint32_t bOff = (PASSES == 3) ? ((p == 1) ? 49152u : 32768u)
                                                : 16384u;
            #pragma unroll
            for (int ks = 0; ks < 4; ks++) {
                uint32_t a[2][4];
                #pragma unroll
                for (int mi = 0; mi < 2; mi++) {
                    int row = wm + mi * 16 + (lane & 15);
                    int un = ks * 2 + (lane >> 4);
                    ldsm4(a[mi], base + aOff + swz(row, un));
                }
                uint32_t b[4][4];
                #pragma unroll
                for (int nc = 0; nc < 4; nc++) {
                    int nr = wn + nc * 16 + ((lane >> 4) << 3) + (lane & 7);
                    int un = ks * 2 + ((lane >> 3) & 1);
                    ldsm4(b[nc], base + bOff + swz(nr, un));
                }
                #pragma unroll
                for (int mi = 0; mi < 2; mi++)
                    #pragma unroll
                    for (int f = 0; f < 8; f++) {
                        uint32_t bb[2] = { b[f >> 1][(f & 1) * 2],
                                           b[f >> 1][(f & 1) * 2 + 1] };
                        mma16816(acc[mi][f], a[mi], bb);
                    }
            }
        }
        __syncthreads();
        if (kc + 2 < NKC) {
            uint32_t nb = sb + (kc & 1) * stageB;
            if (PASSES == 3) {
                cp_tile(nb,         Ah, m0, K, kc + 2, tid);
                cp_tile(nb + 16384, Al, m0, K, kc + 2, tid);
                cp_tile(nb + 32768, Bh, n0, K, kc + 2, tid);
                cp_tile(nb + 49152, Bl, n0, K, kc + 2, tid);
            } else {
                cp_tile(nb,         Ah, m0, K, kc + 2, tid);
                cp_tile(nb + 16384, Bh, n0, K, kc + 2, tid);
            }
        }
        CP_COMMIT();
    }

    // epilogue
    const int g = lane >> 2;
    const int t2 = (lane & 3) * 2;
    #pragma unroll
    for (int mi = 0; mi < 2; mi++) {
        int r0 = m0 + wm + mi * 16 + g;
        int r1 = r0 + 8;
        #pragma unroll
        for (int f = 0; f < 8; f++) {
            int c = n0 + wn + f * 8 + t2;
            float b0 = __ldg(&bias[c]), b1 = __ldg(&bias[c + 1]);
            float v00 = acc[mi][f][0] + b0, v01 = acc[mi][f][1] + b1;
            float v10 = acc[mi][f][2] + b0, v11 = acc[mi][f][3] + b1;
            if (EPI == 0) {
                o32[(size_t)r0 * N + c]     = v00;
                o32[(size_t)r0 * N + c + 1] = v01;
                o32[(size_t)r1 * N + c]     = v10;
                o32[(size_t)r1 * N + c + 1] = v11;
            } else if (EPI == 1) {
                __half2 h0 = __floats2half2_rn(v00 * oscale, v01 * oscale);
                __half2 h1 = __floats2half2_rn(v10 * oscale, v11 * oscale);
                *reinterpret_cast<__half2*>(&o16a[(size_t)r0 * N + c]) = h0;
                *reinterpret_cast<__half2*>(&o16a[(size_t)r1 * N + c]) = h1;
            } else {
                __half h00 = __float2half_rn(v00), h01 = __float2half_rn(v01);
                __half h10 = __float2half_rn(v10), h11 = __float2half_rn(v11);
                *reinterpret_cast<__half2*>(&o16a[(size_t)r0 * N + c]) =
                    __halves2half2(h00, h01);
                *reinterpret_cast<__half2*>(&o16a[(size_t)r1 * N + c]) =
                    __halves2half2(h10, h11);
                __half l00 = __float2half_rn(v00 - __half2float(h00));
                __half l01 = __float2half_rn(v01 - __half2float(h01));
                __half l10 = __float2half_rn(v10 - __half2float(h10));
                __half l11 = __float2half_rn(v11 - __half2float(h11));
                *reinterpret_cast<__half2*>(&o16b[(size_t)r0 * N + c]) =
                    __halves2half2(l00, l01);
                *reinterpret_cast<__half2*>(&o16b[(size_t)r1 * N + c]) =
                    __halves2half2(l10, l11);
            }
        }
    }
}

// ---------------------------------------------------------------------------
// Flash attention on HMMA.
// Block = 128 q rows x 1 head x 1 batch; 8 warps x 16 rows.
// KV tiles of 64; QK 1-pass fp16; PV 3-pass (ph*vh + pl*vh + ph*vl).
// smem: Q 16KB @0; stages @16384 + s*24576: K 8KB, Vh 8KB, Vl 8KB.
// ---------------------------------------------------------------------------
__device__ __forceinline__ void attn_load_kv(uint32_t sb, int s, int b, int h,
                                             int kvTile, const __half* Kg,
                                             const __half* Vhg,
                                             const __half* Vlg, int tid) {
    uint32_t base = sb + 16384 + s * 24576;
    const size_t grow = (size_t)(b * SEQ + kvTile * 64);
    #pragma unroll
    for (int it = 0; it < 2; ++it) {
        int u = tid + it * 256;
        int row = u >> 3, un = u & 7;
        size_t goff = (grow + row) * DM + h * DK + un * 8;
        uint32_t soff = swz(row, un);
        CP_ASYNC16(base + soff,         Kg  + goff);
        CP_ASYNC16(base + 8192 + soff,  Vhg + goff);
        CP_ASYNC16(base + 16384 + soff, Vlg + goff);
    }
}

__global__ __launch_bounds__(256) void attn_mma(
    const __half* __restrict__ Qg, const __half* __restrict__ Kg,
    const __half* __restrict__ Vhg, const __half* __restrict__ Vlg,
    __half* __restrict__ Chg, __half* __restrict__ Clg) {
    extern __shared__ char sm[];
    const uint32_t sb = smem_u32(sm);
    const int tid = threadIdx.x, wid = tid >> 5, lane = tid & 31;
    const int q0 = blockIdx.x * 128;
    const int h = blockIdx.y, b = blockIdx.z;
    const int NT = SEQ / 64;   // 32

    // load Q (128 x 64 fp16)
    {
        const size_t rq = (size_t)(b * SEQ + q0);
        #pragma unroll
        for (int it = 0; it < 4; ++it) {
            int u = tid + it * 256;
            int row = u >> 3, un = u & 7;
            CP_ASYNC16(sb + swz(row, un),
                       Qg + (rq + row) * DM + h * DK + un * 8);
        }
    }
    attn_load_kv(sb, 0, b, h, 0, Kg, Vhg, Vlg, tid);
    CP_COMMIT();
    attn_load_kv(sb, 1, b, h, 1, Kg, Vhg, Vlg, tid);
    CP_COMMIT();

    CP_WAIT1();
    __syncthreads();

    // Q fragments (m16 x k64): aq[ks][4]
    uint32_t aq[4][4];
    #pragma unroll
    for (int ks = 0; ks < 4; ks++) {
        int row = wid * 16 + (lane & 15);
        int un = ks * 2 + (lane >> 4);
        ldsm4(aq[ks], sb + swz(row, un));
    }

    float o[8][4];
    #pragma unroll
    for (int f = 0; f < 8; f++)
        #pragma unroll
        for (int r = 0; r < 4; r++) o[f][r] = 0.0f;
    float m0r = -1e30f, m1r = -1e30f, l0 = 0.0f, l1 = 0.0f;

    const int g = lane >> 2;

    for (int it = 0; it < NT; ++it) {
        if (it > 0) {
            CP_WAIT1();
            __syncthreads();
        }
        const uint32_t kb = sb + 16384 + (it & 1) * 24576;

        // ---- S = Q @ K^T  (m16 x n64) ----
        float sacc[8][4];
        #pragma unroll
        for (int f = 0; f < 8; f++)
            #pragma unroll
            for (int r = 0; r < 4; r++) sacc[f][r] = 0.0f;

        #pragma unroll
        for (int ks = 0; ks < 4; ks++) {
            uint32_t bk[4][4];
            #pragma unroll
            for (int nc = 0; nc < 4; nc++) {
                int nr = nc * 16 + ((lane >> 4) << 3) + (lane & 7);
                int un = ks * 2 + ((lane >> 3) & 1);
                ldsm4(bk[nc], kb + swz(nr, un));
            }
            #pragma unroll
            for (int f = 0; f < 8; f++) {
                uint32_t bb[2] = { bk[f >> 1][(f & 1) * 2],
                                   bk[f >> 1][(f & 1) * 2 + 1] };
                mma16816(sacc[f], aq[ks], bb);
            }
        }

        // ---- online softmax ----
        float t0 = -1e30f, t1 = -1e30f;
        #pragma unroll
        for (int f = 0; f < 8; f++) {
            t0 = fmaxf(t0, fmaxf(sacc[f][0], sacc[f][1]));
            t1 = fmaxf(t1, fmaxf(sacc[f][2], sacc[f][3]));
        }
        t0 = fmaxf(t0, __shfl_xor_sync(0xffffffffu, t0, 1));
        t0 = fmaxf(t0, __shfl_xor_sync(0xffffffffu, t0, 2));
        t1 = fmaxf(t1, __shfl_xor_sync(0xffffffffu, t1, 1));
        t1 = fmaxf(t1, __shfl_xor_sync(0xffffffffu, t1, 2));
        float mn0 = fmaxf(m0r, t0), mn1 = fmaxf(m1r, t1);
        float c0 = ex2f((m0r - mn0) * L2E), c1 = ex2f((m1r - mn1) * L2E);
        m0r = mn0; m1r = mn1;
        l0 *= c0;  l1 *= c1;
        #pragma unroll
        for (int f = 0; f < 8; f++) {
            o[f][0] *= c0; o[f][1] *= c0;
            o[f][2] *= c1; o[f][3] *= c1;
        }

        // ---- P = exp(S - m), split fp16 hi/lo, repack as A fragments ----
        uint32_t ph[4][4], pl[4][4];
        #pragma unroll
        for (int j = 0; j < 4; j++) {
            float p00 = ex2f((sacc[2 * j][0] - mn0) * L2E);
            float p01 = ex2f((sacc[2 * j][1] - mn0) * L2E);
            float p02 = ex2f((sacc[2 * j][2] - mn1) * L2E);
            float p03 = ex2f((sacc[2 * j][3] - mn1) * L2E);
            float p10 = ex2f((sacc[2 * j + 1][0] - mn0) * L2E);
            float p11 = ex2f((sacc[2 * j + 1][1] - mn0) * L2E);
            float p12 = ex2f((sacc[2 * j + 1][2] - mn1) * L2E);
            float p13 = ex2f((sacc[2 * j + 1][3] - mn1) * L2E);
            l0 += p00 + p01 + p10 + p11;
            l1 += p02 + p03 + p12 + p13;
            __half h00 = __float2half_rn(p00), h01 = __float2half_rn(p01);
            __half h02 = __float2half_rn(p02), h03 = __float2half_rn(p03);
            __half h10 = __float2half_rn(p10), h11 = __float2half_rn(p11);
            __half h12 = __float2half_rn(p12), h13 = __float2half_rn(p13);
            ph[j][0] = packh2(h00, h01);
            ph[j][1] = packh2(h02, h03);
            ph[j][2] = packh2(h10, h11);
            ph[j][3] = packh2(h12, h13);
            pl[j][0] = packh2(__float2half_rn(p00 - __half2float(h00)),
                              __float2half_rn(p01 - __half2float(h01)));
            pl[j][1] = packh2(__float2half_rn(p02 - __half2float(h02)),
                              __float2half_rn(p03 - __half2float(h03)));
            pl[j][2] = packh2(__float2half_rn(p10 - __half2float(h10)),
                              __float2half_rn(p11 - __half2float(h11)));
            pl[j][3] = packh2(__float2half_rn(p12 - __half2float(h12)),
                              __float2half_rn(p13 - __half2float(h13)));
        }

        // ---- O += P @ V  (trans ldmatrix on V tiles) ----
        const uint32_t vhb = kb + 8192, vlb = kb + 16384;
        #pragma unroll
        for (int j = 0; j < 4; j++) {
            uint32_t bvh[4][4], bvl[4][4];
            #pragma unroll
            for (int c = 0; c < 4; c++) {
                int kvr = j * 16 + ((lane >> 3) & 1) * 8 + (lane & 7);
                int un = c * 2 + (lane >> 4);
                uint32_t off = swz(kvr, un);
                ldsm4t(bvh[c], vhb + off);
                ldsm4t(bvl[c], vlb + off);
            }
            #pragma unroll
            for (int f = 0; f < 8; f++) {
                uint32_t bh[2] = { bvh[f >> 1][(f & 1) * 2],
                                   bvh[f >> 1][(f & 1) * 2 + 1] };
                uint32_t bl[2] = { bvl[f >> 1][(f & 1) * 2],
                                   bvl[f >> 1][(f & 1) * 2 + 1] };
                mma16816(o[f], ph[j], bh);
                mma16816(o[f], pl[j], bh);
                mma16816(o[f], ph[j], bl);
            }
        }

        __syncthreads();
        if (it + 2 < NT)
            attn_load_kv(sb, it & 1, b, h, it + 2, Kg, Vhg, Vlg, tid);
        CP_COMMIT();
    }

    // ---- finalize: normalize, split fp16 hi/lo, write C ----
    l0 += __shfl_xor_sync(0xffffffffu, l0, 1);
    l0 += __shfl_xor_sync(0xffffffffu, l0, 2);
    l1 += __shfl_xor_sync(0xffffffffu, l1, 1);
    l1 += __shfl_xor_sync(0xffffffffu, l1, 2);
    float inv0 = 1.0f / l0, inv1 = 1.0f / l1;

    const size_t r0 = (size_t)(b * SEQ + q0 + wid * 16 + g);
    const size_t r1 = r0 + 8;
    const int t2 = (lane & 3) * 2;
    #pragma unroll
    for (int f = 0; f < 8; f++) {
        int col = h * DK + f * 8 + t2;
        float v00 = o[f][0] * inv0, v01 = o[f][1] * inv0;
        float v10 = o[f][2] * inv1, v11 = o[f][3] * inv1;
        __half h00 = __float2half_rn(v00), h01 = __float2half_rn(v01);
        __half h10 = __float2half_rn(v10), h11 = __float2half_rn(v11);
        *reinterpret_cast<__half2*>(&Chg[r0 * DM + col]) = __halves2half2(h00, h01);
        *reinterpret_cast<__half2*>(&Chg[r1 * DM + col]) = __halves2half2(h10, h11);
        *reinterpret_cast<__half2*>(&Clg[r0 * DM + col]) =
            __halves2half2(__float2half_rn(v00 - __half2float(h00)),
                           __float2half_rn(v01 - __half2float(h01)));
        *reinterpret_cast<__half2*>(&Clg[r1 * DM + col]) =
            __halves2half2(__float2half_rn(v10 - __half2float(h10)),
                           __float2half_rn(v11 - __half2float(h11)));
    }
}

// ---------------------------------------------------------------------------
// Launch
// ---------------------------------------------------------------------------
extern "C" void kernel_launch(void* const* d_in, const int* in_sizes, int n_in,
                              void* d_out, int out_size) {
    const float* x  = (const float*)d_in[0];
    const float* Wq = (const float*)d_in[1];
    const float* bq = (const float*)d_in[2];
    const float* Wk = (const float*)d_in[3];
    const float* bk = (const float*)d_in[4];
    const float* Wv = (const float*)d_in[5];
    const float* bv = (const float*)d_in[6];
    const float* Wo = (const float*)d_in[7];
    const float* bo = (const float*)d_in[8];
    float* out = (float*)d_out;

    __half *xh, *xl, *q, *k, *vh, *vl, *ch, *cl;
    __half *wqh, *wkh, *wvh, *wvl, *woh, *wol;
    cudaGetSymbolAddress((void**)&xh, g_xh);
    cudaGetSymbolAddress((void**)&xl, g_xl);
    cudaGetSymbolAddress((void**)&q,  g_q);
    cudaGetSymbolAddress((void**)&k,  g_k);
    cudaGetSymbolAddress((void**)&vh, g_vh);
    cudaGetSymbolAddress((void**)&vl, g_vl);
    cudaGetSymbolAddress((void**)&ch, g_ch);
    cudaGetSymbolAddress((void**)&cl, g_cl);
    cudaGetSymbolAddress((void**)&wqh, g_wqh);
    cudaGetSymbolAddress((void**)&wkh, g_wkh);
    cudaGetSymbolAddress((void**)&wvh, g_wvh);
    cudaGetSymbolAddress((void**)&wvl, g_wvl);
    cudaGetSymbolAddress((void**)&woh, g_woh);
    cudaGetSymbolAddress((void**)&wol, g_wol);

    cudaFuncSetAttribute(gemm_mma<1, 1>,
                         cudaFuncAttributeMaxDynamicSharedMemorySize, 65536);
    cudaFuncSetAttribute(gemm_mma<3, 2>,
                         cudaFuncAttributeMaxDynamicSharedMemorySize, 131072);
    cudaFuncSetAttribute(gemm_mma<3, 0>,
                         cudaFuncAttributeMaxDynamicSharedMemorySize, 131072);
    cudaFuncSetAttribute(attn_mma,
                         cudaFuncAttributeMaxDynamicSharedMemorySize, 65536);

    const int NX = MROWS * DM;   // 4M
    const int NW = DM * DM;      // 1M

    split_kernel<<<(NX + 255) / 256, 256>>>(x,  xh,  xl,            NX);
    split_kernel<<<(NW + 255) / 256, 256>>>(Wq, wqh, (__half*)0,    NW);
    split_kernel<<<(NW + 255) / 256, 256>>>(Wk, wkh, (__half*)0,    NW);
    split_kernel<<<(NW + 255) / 256, 256>>>(Wv, wvh, wvl,           NW);
    split_kernel<<<(NW + 255) / 256, 256>>>(Wo, woh, wol,           NW);

    dim3 ggrid(DM / 128, MROWS / 128);   // (8, 32)
    gemm_mma<1, 1><<<ggrid, 256, 65536>>>(xh, (const __half*)0, wqh,
        (const __half*)0, bq, q, (__half*)0, (float*)0, MROWS, DM, DM, 0.125f);
    gemm_mma<1, 1><<<ggrid, 256, 65536>>>(xh, (const __half*)0, wkh,
        (const __half*)0, bk, k, (__half*)0, (float*)0, MROWS, DM, DM, 1.0f);
    gemm_mma<3, 2><<<ggrid, 256, 131072>>>(xh, xl, wvh, wvl, bv,
        vh, vl, (float*)0, MROWS, DM, DM, 1.0f);

    dim3 agrid(SEQ / 128, NH, BATCH);    // (16, 16, 2)
    attn_mma<<<agrid, 256, 65536>>>(q, k, vh, vl, ch, cl);

    gemm_mma<3, 0><<<ggrid, 256, 131072>>>(ch, cl, woh, wol, bo,
        (__half*)0, (__half*)0, out, MROWS, DM, DM, 1.0f);
}

// round 4
// speedup vs baseline: 10.0564x; 1.3560x over previous
#include <cuda_runtime.h>
#include <cuda_fp16.h>
#include <math.h>
#include <stdint.h>

#define BATCH 2
#define SEQ   2048
#define DM    1024
#define NH    16
#define DK    64
#define MROWS (BATCH * SEQ)   // 4096
#define L2E   1.44269504f

// ---------------------------------------------------------------------------
// Scratch (device globals — no allocations allowed)
// ---------------------------------------------------------------------------
__device__ __half g_xh[MROWS * DM];
__device__ __half g_xl[MROWS * DM];
__device__ __half g_q [MROWS * DM];   // pre-scaled by 1/8
__device__ __half g_k [MROWS * DM];
__device__ __half g_vh[MROWS * DM];
__device__ __half g_ch[MROWS * DM];
__device__ __half g_cl[MROWS * DM];
__device__ __half g_wqh[DM * DM];
__device__ __half g_wkh[DM * DM];
__device__ __half g_wvh[DM * DM];
__device__ __half g_wvl[DM * DM];
__device__ __half g_woh[DM * DM];
__device__ __half g_wol[DM * DM];

// ---------------------------------------------------------------------------
// Base-ISA PTX helpers (compute_103-safe: mma.sync / ldmatrix / cp.async)
// ---------------------------------------------------------------------------
__device__ __forceinline__ uint32_t smem_u32(const void* p) {
    uint32_t a;
    asm("{ .reg .u64 t; cvta.to.shared.u64 t, %1; cvt.u32.u64 %0, t; }"
        : "=r"(a) : "l"(p));
    return a;
}

#define CP_ASYNC16(dst, src) \
    asm volatile("cp.async.cg.shared.global [%0], [%1], 16;" \
                 :: "r"(dst), "l"(src) : "memory")
#define CP_COMMIT() asm volatile("cp.async.commit_group;" ::: "memory")
#define CP_WAIT1()  asm volatile("cp.async.wait_group 1;" ::: "memory")
#define CP_WAIT2()  asm volatile("cp.async.wait_group 2;" ::: "memory")

__device__ __forceinline__ void ldsm4(uint32_t* r, uint32_t addr) {
    asm volatile("ldmatrix.sync.aligned.m8n8.x4.shared.b16 {%0,%1,%2,%3}, [%4];"
                 : "=r"(r[0]), "=r"(r[1]), "=r"(r[2]), "=r"(r[3]) : "r"(addr));
}
__device__ __forceinline__ void ldsm4t(uint32_t* r, uint32_t addr) {
    asm volatile("ldmatrix.sync.aligned.m8n8.x4.trans.shared.b16 {%0,%1,%2,%3}, [%4];"
                 : "=r"(r[0]), "=r"(r[1]), "=r"(r[2]), "=r"(r[3]) : "r"(addr));
}

__device__ __forceinline__ void mma16816(float* c, const uint32_t* a,
                                         const uint32_t* b) {
    asm volatile(
        "mma.sync.aligned.m16n8k16.row.col.f32.f16.f16.f32 "
        "{%0,%1,%2,%3},{%4,%5,%6,%7},{%8,%9},{%0,%1,%2,%3};"
        : "+f"(c[0]), "+f"(c[1]), "+f"(c[2]), "+f"(c[3])
        : "r"(a[0]), "r"(a[1]), "r"(a[2]), "r"(a[3]), "r"(b[0]), "r"(b[1]));
}

__device__ __forceinline__ float ex2f(float x) {
    float y;
    asm("ex2.approx.f32 %0, %1;" : "=f"(y) : "f"(x));
    return y;
}

// exp2 of two fp32 values -> packed fp16x2 (one cvt + one MUFU f16x2 op)
__device__ __forceinline__ uint32_t exp2_h2(float ea, float eb) {
    __half2 x = __floats2half2_rn(ea, eb);
    uint32_t xi = *reinterpret_cast<uint32_t*>(&x);
    uint32_t r;
    asm("ex2.approx.f16x2 %0, %1;" : "=r"(r) : "r"(xi));
    return r;
}

__device__ __forceinline__ uint32_t packh2(__half a, __half b) {
    __half2 t = __halves2half2(a, b);
    return *reinterpret_cast<uint32_t*>(&t);
}

// swizzled smem offset for (row, 16B-unit): rows are 8 units (128B) wide
__device__ __forceinline__ uint32_t swz(int row, int un) {
    return (uint32_t)(((row << 3) + (un ^ (row & 7))) << 4);
}

// ---------------------------------------------------------------------------
// split fp32 -> fp16 hi (+ optional lo), float4-vectorized
// ---------------------------------------------------------------------------
template <bool LO>
__global__ void split_kernel4(const float4* __restrict__ in,
                              uint2* __restrict__ hi,
                              uint2* __restrict__ lo, int n4) {
    int i = blockIdx.x * 256 + threadIdx.x;
    if (i < n4) {
        float4 v = in[i];
        __half2 ha = __floats2half2_rn(v.x, v.y);
        __half2 hb = __floats2half2_rn(v.z, v.w);
        hi[i] = make_uint2(*reinterpret_cast<uint32_t*>(&ha),
                           *reinterpret_cast<uint32_t*>(&hb));
        if (LO) {
            __half2 la = __floats2half2_rn(v.x - __low2float(ha),
                                           v.y - __high2float(ha));
            __half2 lb = __floats2half2_rn(v.z - __low2float(hb),
                                           v.w - __high2float(hb));
            lo[i] = make_uint2(*reinterpret_cast<uint32_t*>(&la),
                               *reinterpret_cast<uint32_t*>(&lb));
        }
    }
}

// ---------------------------------------------------------------------------
// HMMA GEMM: C[M,N] = A[M,K] @ W[N,K]^T + bias
// PASSES=1: ah*bh.  PASSES=3: ah*bh + ah*bl + al*bh (fp32 accum throughout).
// EPI: 0 = fp32 out; 1 = fp16 out (scaled); 2 = fp16 hi/lo pair out.
// Block tile 128x128, BK=64, 8 warps (warp tile 32x64), cp.async double buffer.
// ---------------------------------------------------------------------------
__device__ __forceinline__ void cp_tile(uint32_t dstBase, const __half* src,
                                        int rowBase, int K, int kc, int tid) {
    #pragma unroll
    for (int it = 0; it < 4; ++it) {
        int u = tid + it * 256;
        int row = u >> 3, un = u & 7;
        const __half* g = src + (size_t)(rowBase + row) * K + kc * 64 + un * 8;
        CP_ASYNC16(dstBase + swz(row, un), g);
    }
}

template <int PASSES, int EPI>
__global__ __launch_bounds__(256) void gemm_mma(
    const __half* __restrict__ Ah, const __half* __restrict__ Al,
    const __half* __restrict__ Bh, const __half* __restrict__ Bl,
    const float* __restrict__ bias,
    __half* __restrict__ o16a, __half* __restrict__ o16b,
    float* __restrict__ o32, int M, int N, int K, float oscale) {
    extern __shared__ char sm[];
    const uint32_t sb = smem_u32(sm);
    const int NT = (PASSES == 3) ? 4 : 2;
    const uint32_t stageB = (uint32_t)NT * 16384u;
    const int tid = threadIdx.x, wid = tid >> 5, lane = tid & 31;
    const int n0 = blockIdx.x * 128, m0 = blockIdx.y * 128;
    const int wm = (wid & 3) * 32, wn = (wid >> 2) * 64;
    const int NKC = K / 64;

    float acc[2][8][4];
    #pragma unroll
    for (int i = 0; i < 2; i++)
        #pragma unroll
        for (int f = 0; f < 8; f++)
            #pragma unroll
            for (int r = 0; r < 4; r++) acc[i][f][r] = 0.0f;

    #pragma unroll
    for (int s = 0; s < 2; s++) {
        uint32_t base = sb + s * stageB;
        if (PASSES == 3) {
            cp_tile(base,          Ah, m0, K, s, tid);
            cp_tile(base + 16384,  Al, m0, K, s, tid);
            cp_tile(base + 32768,  Bh, n0, K, s, tid);
            cp_tile(base + 49152,  Bl, n0, K, s, tid);
        } else {
            cp_tile(base,          Ah, m0, K, s, tid);
            cp_tile(base + 16384,  Bh, n0, K, s, tid);
        }
        CP_COMMIT();
    }

    for (int kc = 0; kc < NKC; kc++) {
        CP_WAIT1();
        __syncthreads();
        const uint32_t base = sb + (kc & 1) * stageB;

        #pragma unroll
        for (int p = 0; p < PASSES; p++) {
            const uint32_t aOff = (PASSES == 3 && p == 2) ? 16384u : 0u;
            const uint32_t bOff = (PASSES == 3) ? ((p == 1) ? 49152u : 32768u)
                                                : 16384u;
            #pragma unroll
            for (int ks = 0; ks < 4; ks++) {
                uint32_t a[2][4];
                #pragma unroll
                for (int mi = 0; mi < 2; mi++) {
                    int row = wm + mi * 16 + (lane & 15);
                    int un = ks * 2 + (lane >> 4);
                    ldsm4(a[mi], base + aOff + swz(row, un));
                }
                uint32_t b[4][4];
                #pragma unroll
                for (int nc = 0; nc < 4; nc++) {
                    int nr = wn + nc * 16 + ((lane >> 4) << 3) + (lane & 7);
                    int un = ks * 2 + ((lane >> 3) & 1);
                    ldsm4(b[nc], base + bOff + swz(nr, un));
                }
                #pragma unroll
                for (int mi = 0; mi < 2; mi++)
                    #pragma unroll
                    for (int f = 0; f < 8; f++) {
                        uint32_t bb[2] = { b[f >> 1][(f & 1) * 2],
                                           b[f >> 1][(f & 1) * 2 + 1] };
                        mma16816(acc[mi][f], a[mi], bb);
                    }
            }
        }
        __syncthreads();
        if (kc + 2 < NKC) {
            uint32_t nb = sb + (kc & 1) * stageB;
            if (PASSES == 3) {
                cp_tile(nb,         Ah, m0, K, kc + 2, tid);
                cp_tile(nb + 16384, Al, m0, K, kc + 2, tid);
                cp_tile(nb + 32768, Bh, n0, K, kc + 2, tid);
                cp_tile(nb + 49152, Bl, n0, K, kc + 2, tid);
            } else {
                cp_tile(nb,         Ah, m0, K, kc + 2, tid);
                cp_tile(nb + 16384, Bh, n0, K, kc + 2, tid);
            }
        }
        CP_COMMIT();
    }

    const int g = lane >> 2;
    const int t2 = (lane & 3) * 2;
    #pragma unroll
    for (int mi = 0; mi < 2; mi++) {
        int r0 = m0 + wm + mi * 16 + g;
        int r1 = r0 + 8;
        #pragma unroll
        for (int f = 0; f < 8; f++) {
            int c = n0 + wn + f * 8 + t2;
            float b0 = __ldg(&bias[c]), b1 = __ldg(&bias[c + 1]);
            float v00 = acc[mi][f][0] + b0, v01 = acc[mi][f][1] + b1;
            float v10 = acc[mi][f][2] + b0, v11 = acc[mi][f][3] + b1;
            if (EPI == 0) {
                o32[(size_t)r0 * N + c]     = v00;
                o32[(size_t)r0 * N + c + 1] = v01;
                o32[(size_t)r1 * N + c]     = v10;
                o32[(size_t)r1 * N + c + 1] = v11;
            } else if (EPI == 1) {
                __half2 h0 = __floats2half2_rn(v00 * oscale, v01 * oscale);
                __half2 h1 = __floats2half2_rn(v10 * oscale, v11 * oscale);
                *reinterpret_cast<__half2*>(&o16a[(size_t)r0 * N + c]) = h0;
                *reinterpret_cast<__half2*>(&o16a[(size_t)r1 * N + c]) = h1;
            } else {
                __half h00 = __float2half_rn(v00), h01 = __float2half_rn(v01);
                __half h10 = __float2half_rn(v10), h11 = __float2half_rn(v11);
                *reinterpret_cast<__half2*>(&o16a[(size_t)r0 * N + c]) =
                    __halves2half2(h00, h01);
                *reinterpret_cast<__half2*>(&o16a[(size_t)r1 * N + c]) =
                    __halves2half2(h10, h11);
                __half l00 = __float2half_rn(v00 - __half2float(h00));
                __half l01 = __float2half_rn(v01 - __half2float(h01));
                __half l10 = __float2half_rn(v10 - __half2float(h10));
                __half l11 = __float2half_rn(v11 - __half2float(h11));
                *reinterpret_cast<__half2*>(&o16b[(size_t)r0 * N + c]) =
                    __halves2half2(l00, l01);
                *reinterpret_cast<__half2*>(&o16b[(size_t)r1 * N + c]) =
                    __halves2half2(l10, l11);
            }
        }
    }
}

// ---------------------------------------------------------------------------
// Flash attention on HMMA (fp16 P, 1-pass PV, row-sum via ones-MMA).
// Block = 128 q rows x 1 head x 1 batch; 8 warps x 16 rows.
// KV tiles of 64, 3-deep cp.async pipeline.
// smem: Q 16KB @0; stage s @16384 + s*16384: K 8KB, Vh 8KB.
// ---------------------------------------------------------------------------
__device__ __forceinline__ void attn_load_kv(uint32_t sb, int s, int b, int h,
                                             int kvTile, const __half* Kg,
                                             const __half* Vhg, int tid) {
    uint32_t base = sb + 16384 + s * 16384;
    const size_t grow = (size_t)(b * SEQ + kvTile * 64);
    #pragma unroll
    for (int it = 0; it < 2; ++it) {
        int u = tid + it * 256;
        int row = u >> 3, un = u & 7;
        size_t goff = (grow + row) * DM + h * DK + un * 8;
        uint32_t soff = swz(row, un);
        CP_ASYNC16(base + soff,        Kg  + goff);
        CP_ASYNC16(base + 8192 + soff, Vhg + goff);
    }
}

__global__ __launch_bounds__(256) void attn_mma(
    const __half* __restrict__ Qg, const __half* __restrict__ Kg,
    const __half* __restrict__ Vhg,
    __half* __restrict__ Chg, __half* __restrict__ Clg) {
    extern __shared__ char sm[];
    const uint32_t sb = smem_u32(sm);
    const int tid = threadIdx.x, wid = tid >> 5, lane = tid & 31;
    const int q0 = blockIdx.x * 128;
    const int h = blockIdx.y, b = blockIdx.z;
    const int NT = SEQ / 64;   // 32

    // prologue: Q + KV tiles 0,1,2 (3 commit groups)
    {
        const size_t rq = (size_t)(b * SEQ + q0);
        #pragma unroll
        for (int it = 0; it < 4; ++it) {
            int u = tid + it * 256;
            int row = u >> 3, un = u & 7;
            CP_ASYNC16(sb + swz(row, un),
                       Qg + (rq + row) * DM + h * DK + un * 8);
        }
    }
    attn_load_kv(sb, 0, b, h, 0, Kg, Vhg, tid);
    CP_COMMIT();
    attn_load_kv(sb, 1, b, h, 1, Kg, Vhg, tid);
    CP_COMMIT();
    attn_load_kv(sb, 2, b, h, 2, Kg, Vhg, tid);
    CP_COMMIT();

    CP_WAIT2();
    __syncthreads();

    // Q fragments (m16 x k64)
    uint32_t aq[4][4];
    #pragma unroll
    for (int ks = 0; ks < 4; ks++) {
        int row = wid * 16 + (lane & 15);
        int un = ks * 2 + (lane >> 4);
        ldsm4(aq[ks], sb + swz(row, un));
    }

    float o[8][4];
    #pragma unroll
    for (int f = 0; f < 8; f++)
        #pragma unroll
        for (int r = 0; r < 4; r++) o[f][r] = 0.0f;
    float m0r = -1e30f, m1r = -1e30f, l0 = 0.0f, l1 = 0.0f;

    const uint32_t onesh2 = packh2(__float2half_rn(1.0f), __float2half_rn(1.0f));
    const uint32_t bones[2] = { onesh2, onesh2 };
    const int g = lane >> 2;

    for (int it = 0; it < NT; ++it) {
        if (it > 0) {
            CP_WAIT2();
            __syncthreads();
        }
        const uint32_t kb = sb + 16384 + (it % 3) * 16384;

        // ---- S = Q @ K^T ----
        float sacc[8][4];
        #pragma unroll
        for (int f = 0; f < 8; f++)
            #pragma unroll
            for (int r = 0; r < 4; r++) sacc[f][r] = 0.0f;

        #pragma unroll
        for (int ks = 0; ks < 4; ks++) {
            uint32_t bk[4][4];
            #pragma unroll
            for (int nc = 0; nc < 4; nc++) {
                int nr = nc * 16 + ((lane >> 4) << 3) + (lane & 7);
                int un = ks * 2 + ((lane >> 3) & 1);
                ldsm4(bk[nc], kb + swz(nr, un));
            }
            #pragma unroll
            for (int f = 0; f < 8; f++) {
                uint32_t bb[2] = { bk[f >> 1][(f & 1) * 2],
                                   bk[f >> 1][(f & 1) * 2 + 1] };
                mma16816(sacc[f], aq[ks], bb);
            }
        }

        // ---- online softmax (fp16 P via ex2.approx.f16x2) ----
        float t0 = -1e30f, t1 = -1e30f;
        #pragma unroll
        for (int f = 0; f < 8; f++) {
            t0 = fmaxf(t0, fmaxf(sacc[f][0], sacc[f][1]));
            t1 = fmaxf(t1, fmaxf(sacc[f][2], sacc[f][3]));
        }
        t0 = fmaxf(t0, __shfl_xor_sync(0xffffffffu, t0, 1));
        t0 = fmaxf(t0, __shfl_xor_sync(0xffffffffu, t0, 2));
        t1 = fmaxf(t1, __shfl_xor_sync(0xffffffffu, t1, 1));
        t1 = fmaxf(t1, __shfl_xor_sync(0xffffffffu, t1, 2));
        float mn0 = fmaxf(m0r, t0), mn1 = fmaxf(m1r, t1);
        float c0 = ex2f((m0r - mn0) * L2E), c1 = ex2f((m1r - mn1) * L2E);
        m0r = mn0; m1r = mn1;
        #pragma unroll
        for (int f = 0; f < 8; f++) {
            o[f][0] *= c0; o[f][1] *= c0;
            o[f][2] *= c1; o[f][3] *= c1;
        }

        uint32_t ph[4][4];
        #pragma unroll
        for (int j = 0; j < 4; j++) {
            ph[j][0] = exp2_h2((sacc[2 * j][0] - mn0) * L2E,
                               (sacc[2 * j][1] - mn0) * L2E);
            ph[j][1] = exp2_h2((sacc[2 * j][2] - mn1) * L2E,
                               (sacc[2 * j][3] - mn1) * L2E);
            ph[j][2] = exp2_h2((sacc[2 * j + 1][0] - mn0) * L2E,
                               (sacc[2 * j + 1][1] - mn0) * L2E);
            ph[j][3] = exp2_h2((sacc[2 * j + 1][2] - mn1) * L2E,
                               (sacc[2 * j + 1][3] - mn1) * L2E);
        }

        // ---- l += row-sum(P) via ones-MMA (consistent with PV numerator) ----
        float lacc[4] = {0.0f, 0.0f, 0.0f, 0.0f};
        #pragma unroll
        for (int j = 0; j < 4; j++) mma16816(lacc, ph[j], bones);
        l0 = l0 * c0 + lacc[0];
        l1 = l1 * c1 + lacc[2];

        // ---- O += P @ V (1 pass) ----
        const uint32_t vhb = kb + 8192;
        #pragma unroll
        for (int j = 0; j < 4; j++) {
            uint32_t bvh[4][4];
            #pragma unroll
            for (int c = 0; c < 4; c++) {
                int kvr = j * 16 + ((lane >> 3) & 1) * 8 + (lane & 7);
                int un = c * 2 + (lane >> 4);
                ldsm4t(bvh[c], vhb + swz(kvr, un));
            }
            #pragma unroll
            for (int f = 0; f < 8; f++) {
                uint32_t bh[2] = { bvh[f >> 1][(f & 1) * 2],
                                   bvh[f >> 1][(f & 1) * 2 + 1] };
                mma16816(o[f], ph[j], bh);
            }
        }

        __syncthreads();
        if (it + 3 < NT)
            attn_load_kv(sb, it % 3, b, h, it + 3, Kg, Vhg, tid);
        CP_COMMIT();
    }

    // ---- finalize: normalize, split fp16 hi/lo, write C ----
    float inv0 = 1.0f / l0, inv1 = 1.0f / l1;

    const size_t r0 = (size_t)(b * SEQ + q0 + wid * 16 + g);
    const size_t r1 = r0 + 8;
    const int t2 = (lane & 3) * 2;
    #pragma unroll
    for (int f = 0; f < 8; f++) {
        int col = h * DK + f * 8 + t2;
        float v00 = o[f][0] * inv0, v01 = o[f][1] * inv0;
        float v10 = o[f][2] * inv1, v11 = o[f][3] * inv1;
        __half h00 = __float2half_rn(v00), h01 = __float2half_rn(v01);
        __half h10 = __float2half_rn(v10), h11 = __float2half_rn(v11);
        *reinterpret_cast<__half2*>(&Chg[r0 * DM + col]) = __halves2half2(h00, h01);
        *reinterpret_cast<__half2*>(&Chg[r1 * DM + col]) = __halves2half2(h10, h11);
        *reinterpret_cast<__half2*>(&Clg[r0 * DM + col]) =
            __halves2half2(__float2half_rn(v00 - __half2float(h00)),
                           __float2half_rn(v01 - __half2float(h01)));
        *reinterpret_cast<__half2*>(&Clg[r1 * DM + col]) =
            __halves2half2(__float2half_rn(v10 - __half2float(h10)),
                           __float2half_rn(v11 - __half2float(h11)));
    }
}

// ---------------------------------------------------------------------------
// Launch
// ---------------------------------------------------------------------------
extern "C" void kernel_launch(void* const* d_in, const int* in_sizes, int n_in,
                              void* d_out, int out_size) {
    const float* x  = (const float*)d_in[0];
    const float* Wq = (const float*)d_in[1];
    const float* bq = (const float*)d_in[2];
    const float* Wk = (const float*)d_in[3];
    const float* bk = (const float*)d_in[4];
    const float* Wv = (const float*)d_in[5];
    const float* bv = (const float*)d_in[6];
    const float* Wo = (const float*)d_in[7];
    const float* bo = (const float*)d_in[8];
    float* out = (float*)d_out;

    __half *xh, *xl, *q, *k, *vh, *ch, *cl;
    __half *wqh, *wkh, *wvh, *wvl, *woh, *wol;
    cudaGetSymbolAddress((void**)&xh, g_xh);
    cudaGetSymbolAddress((void**)&xl, g_xl);
    cudaGetSymbolAddress((void**)&q,  g_q);
    cudaGetSymbolAddress((void**)&k,  g_k);
    cudaGetSymbolAddress((void**)&vh, g_vh);
    cudaGetSymbolAddress((void**)&ch, g_ch);
    cudaGetSymbolAddress((void**)&cl, g_cl);
    cudaGetSymbolAddress((void**)&wqh, g_wqh);
    cudaGetSymbolAddress((void**)&wkh, g_wkh);
    cudaGetSymbolAddress((void**)&wvh, g_wvh);
    cudaGetSymbolAddress((void**)&wvl, g_wvl);
    cudaGetSymbolAddress((void**)&woh, g_woh);
    cudaGetSymbolAddress((void**)&wol, g_wol);

    cudaFuncSetAttribute(gemm_mma<1, 1>,
                         cudaFuncAttributeMaxDynamicSharedMemorySize, 65536);
    cudaFuncSetAttribute(gemm_mma<3, 1>,
                         cudaFuncAttributeMaxDynamicSharedMemorySize, 131072);
    cudaFuncSetAttribute(gemm_mma<3, 0>,
                         cudaFuncAttributeMaxDynamicSharedMemorySize, 131072);
    cudaFuncSetAttribute(attn_mma,
                         cudaFuncAttributeMaxDynamicSharedMemorySize, 65536);

    const int NX4 = MROWS * DM / 4;   // 1M
    const int NW4 = DM * DM / 4;      // 256K

    split_kernel4<true ><<<(NX4 + 255) / 256, 256>>>(
        (const float4*)x, (uint2*)xh, (uint2*)xl, NX4);
    split_kernel4<false><<<(NW4 + 255) / 256, 256>>>(
        (const float4*)Wq, (uint2*)wqh, (uint2*)0, NW4);
    split_kernel4<false><<<(NW4 + 255) / 256, 256>>>(
        (const float4*)Wk, (uint2*)wkh, (uint2*)0, NW4);
    split_kernel4<true ><<<(NW4 + 255) / 256, 256>>>(
        (const float4*)Wv, (uint2*)wvh, (uint2*)wvl, NW4);
    split_kernel4<true ><<<(NW4 + 255) / 256, 256>>>(
        (const float4*)Wo, (uint2*)woh, (uint2*)wol, NW4);

    dim3 ggrid(DM / 128, MROWS / 128);   // (8, 32)
    gemm_mma<1, 1><<<ggrid, 256, 65536>>>(xh, (const __half*)0, wqh,
        (const __half*)0, bq, q, (__half*)0, (float*)0, MROWS, DM, DM, 0.125f);
    gemm_mma<1, 1><<<ggrid, 256, 65536>>>(xh, (const __half*)0, wkh,
        (const __half*)0, bk, k, (__half*)0, (float*)0, MROWS, DM, DM, 1.0f);
    gemm_mma<3, 1><<<ggrid, 256, 131072>>>(xh, xl, wvh, wvl, bv,
        vh, (__half*)0, (float*)0, MROWS, DM, DM, 1.0f);

    dim3 agrid(SEQ / 128, NH, BATCH);    // (16, 16, 2)
    attn_mma<<<agrid, 256, 65536>>>(q, k, vh, ch, cl);

    gemm_mma<3, 0><<<ggrid, 256, 131072>>>(ch, cl, woh, wol, bo,
        (__half*)0, (__half*)0, out, MROWS, DM, DM, 1.0f);
}